// round 14
// baseline (speedup 1.0000x reference)
#include <cuda_runtime.h>
#include <cuda_fp16.h>
#include <math.h>

// ---------------- problem constants ----------------
#define MAX_NODES 50000
#define MAX_EDGES 800000

// fp16-compressed per-node records (channel order): per lane 12 halves = uint4 + uint2 (24B)
__device__ uint4 g_node4[MAX_NODES * 32];
__device__ uint2 g_node2[MAX_NODES * 32];

// src-sorted edge metadata: (src, dst, e, pad)
__device__ int4 g_meta[MAX_EDGES];
__device__ int g_cnt[MAX_NODES];
__device__ int g_off[MAX_NODES];
__device__ int g_pos[MAX_NODES];

// ---- constants derived from the reference's (non-standard) CG formula ----
#define ALPHA0 0.125f
#define ALPHA1 0.10206207261596575f
#define D0 0.6666666666666666f
#define D1 0.3333333333333333f
#define E0 0.6963106238227914f
#define E1 0.17407765595569785f
#define N1 0.48888007f
#define N2 0.04704256f
#define N3 0.06111001f
#define N4 0.12222002f

#define NPW 4   // nodes per warp in precompute

static __device__ __forceinline__ unsigned pack2(float a, float b) {
    half2 h = __floats2half2_rn(a, b);
    return *reinterpret_cast<unsigned*>(&h);
}
static __device__ __forceinline__ float2 unpack2(unsigned u) {
    half2 h = *reinterpret_cast<half2*>(&u);
    return __half22float2(h);
}

// ---------------- counting sort of edges by src ----------------
__global__ void hist_kernel(const int* __restrict__ eidx, int n_edges) {
    int e = blockIdx.x * blockDim.x + threadIdx.x;
    if (e < n_edges) atomicAdd(&g_cnt[eidx[e]], 1);
}

__global__ void scan_kernel(int n_nodes) {   // single block, 1024 threads
    __shared__ int ssum[1024];
    int t = threadIdx.x;
    const int SEG = (MAX_NODES + 1023) / 1024;
    int base = t * SEG;
    int s = 0;
    for (int i = 0; i < SEG; i++) {
        int idx = base + i;
        if (idx < n_nodes) s += g_cnt[idx];
    }
    ssum[t] = s;
    __syncthreads();
    for (int d = 1; d < 1024; d <<= 1) {
        int v = (t >= d) ? ssum[t - d] : 0;
        __syncthreads();
        ssum[t] += v;
        __syncthreads();
    }
    int run = (t == 0) ? 0 : ssum[t - 1];
    for (int i = 0; i < SEG; i++) {
        int idx = base + i;
        if (idx < n_nodes) {
            g_off[idx] = run;
            g_pos[idx] = run;
            run += g_cnt[idx];
        }
    }
}

__global__ void scatter_kernel(const int* __restrict__ eidx, int n_edges) {
    int e = blockIdx.x * blockDim.x + threadIdx.x;
    if (e < n_edges) {
        int s = eidx[e];
        int d = eidx[n_edges + e];
        int p = atomicAdd(&g_pos[s], 1);
        g_meta[p] = make_int4(s, d, e, 0);
    }
}

// ---------------- per-node precompute: 4 nodes/warp, lane = channel ----------------
__global__ void __launch_bounds__(256) precompute_kernel(const float* __restrict__ feat,
                                                         const float* __restrict__ W,
                                                         int n_nodes) {
    __shared__ float Ws[5 * 1024];
    __shared__ float4 xs[8][NPW * 32];

    for (int i = threadIdx.x; i < 5 * 1024; i += blockDim.x) {
        int p = i >> 10;
        float s = (p == 0 || p == 3) ? ALPHA0 : ALPHA1;
        Ws[i] = s * W[i];
    }
    __syncthreads();

    int lane = threadIdx.x & 31;
    int wl   = threadIdx.x >> 5;
    int warp = (blockIdx.x * blockDim.x + threadIdx.x) >> 5;
    int nwarp = (gridDim.x * blockDim.x) >> 5;

    for (int nb = warp * NPW; nb < n_nodes; nb += nwarp * NPW) {
        #pragma unroll
        for (int nn = 0; nn < NPW; nn++) {
            int n = nb + nn;
            float4 v = make_float4(0.f, 0.f, 0.f, 0.f);
            if (n < n_nodes) {
                const float* x = feat + (size_t)n * 128;
                v.x = x[lane];
                v.y = x[32 + 3 * lane];
                v.z = x[33 + 3 * lane];
                v.w = x[34 + 3 * lane];
            }
            xs[wl][nn * 32 + lane] = v;
        }
        __syncwarp();

        float a1[NPW], a2[NPW], b3[NPW][3], b4[NPW][3], b5[NPW][3];
        #pragma unroll
        for (int nn = 0; nn < NPW; nn++) {
            a1[nn] = 0.f; a2[nn] = 0.f;
            #pragma unroll
            for (int k = 0; k < 3; k++) { b3[nn][k] = 0.f; b4[nn][k] = 0.f; b5[nn][k] = 0.f; }
        }

        #pragma unroll 4
        for (int u = 0; u < 32; u++) {
            float w0 = Ws[          u * 32 + lane];
            float w1 = Ws[1024 +    u * 32 + lane];
            float w2 = Ws[2048 +    u * 32 + lane];
            float w3 = Ws[3072 +    u * 32 + lane];
            float w4 = Ws[4096 +    u * 32 + lane];
            #pragma unroll
            for (int nn = 0; nn < NPW; nn++) {
                float4 v = xs[wl][nn * 32 + u];   // broadcast
                a1[nn] = fmaf(v.x, w0, a1[nn]);
                a2[nn] = fmaf(v.x, w1, a2[nn]);
                b3[nn][0] = fmaf(v.y, w2, b3[nn][0]);
                b3[nn][1] = fmaf(v.z, w2, b3[nn][1]);
                b3[nn][2] = fmaf(v.w, w2, b3[nn][2]);
                b4[nn][0] = fmaf(v.y, w3, b4[nn][0]);
                b4[nn][1] = fmaf(v.z, w3, b4[nn][1]);
                b4[nn][2] = fmaf(v.w, w3, b4[nn][2]);
                b5[nn][0] = fmaf(v.y, w4, b5[nn][0]);
                b5[nn][1] = fmaf(v.z, w4, b5[nn][1]);
                b5[nn][2] = fmaf(v.w, w4, b5[nn][2]);
            }
        }

        #pragma unroll
        for (int nn = 0; nn < NPW; nn++) {
            int n = nb + nn;
            if (n >= n_nodes) break;
            float c30 = b3[nn][0] * D0, c31 = b3[nn][1] * D1, c32 = b3[nn][2] * D0;
            float c40 = b4[nn][0] * E0, c41 = b4[nn][1] * E1, c42 = b4[nn][2] * E0;
            uint4 p;
            p.x = pack2(a1[nn], a2[nn]);
            p.y = pack2(c30, c31);
            p.z = pack2(c32, c40);
            p.w = pack2(c41, c42);
            uint2 q;
            q.x = pack2(b5[nn][0], b5[nn][1]);
            q.y = pack2(b5[nn][2], 0.f);
            g_node4[n * 32 + lane] = p;
            g_node2[n * 32 + lane] = q;
        }
        __syncwarp();
    }
}

// ---------------- push kernel over src-sorted chunks: R10 body, L1-friendly gather order ----------------
__global__ void __launch_bounds__(256) edge_kernel(const float* __restrict__ sh,
                                                   float* __restrict__ out,
                                                   int n_edges) {
    __shared__ __align__(16) float buf[8][128];
    const unsigned FULL = 0xFFFFFFFFu;
    int lane  = threadIdx.x & 31;
    int wl    = threadIdx.x >> 5;
    int warp  = (blockIdx.x * blockDim.x + threadIdx.x) >> 5;
    int nwarp = (gridDim.x * blockDim.x) >> 5;
    float* b = buf[wl];

    int n_chunks = (n_edges + 31) / 32;
    for (int c = warp; c < n_chunks; c += nwarp) {
        int base = c * 32;
        int m = min(32, n_edges - base);
        int4 meta = g_meta[base + ((lane < m) ? lane : 0)];   // coalesced chunk header

        int e0 = __shfl_sync(FULL, meta.z, 0);
        float sv = (lane < 9) ? sh[(size_t)e0 * 9 + lane] : 0.f;

        for (int j = 0; j < m; j++) {
            int src = __shfl_sync(FULL, meta.x, j);
            int dst = __shfl_sync(FULL, meta.y, j);

            // record gather: same-src runs stay in this warp -> L1 hits after first touch
            uint4 rp = g_node4[src * 32 + lane];
            uint2 rq = g_node2[src * 32 + lane];

            // prefetch next edge's sh while the gather is in flight
            float nsv = 0.f;
            if (j + 1 < m) {
                int e1 = __shfl_sync(FULL, meta.z, j + 1);
                nsv = (lane < 9) ? sh[(size_t)e1 * 9 + lane] : 0.f;
            }

            // broadcast sh components
            float s0  = __shfl_sync(FULL, sv, 0);
            float s1x = __shfl_sync(FULL, sv, 1);
            float s1y = __shfl_sync(FULL, sv, 2);
            float s1z = __shfl_sync(FULL, sv, 3);
            float q0  = __shfl_sync(FULL, sv, 4);
            float q1v = __shfl_sync(FULL, sv, 5);
            float q2  = __shfl_sync(FULL, sv, 6);
            float q3  = __shfl_sync(FULL, sv, 7);
            float q4  = __shfl_sync(FULL, sv, 8);

            float n2q2 = N2 * q2;
            float n1q4 = N1 * q4;
            float n1q0 = N1 * q0;
            float n3q1 = N3 * q1v;
            float n4q1 = N4 * q1v;
            float n3q3 = N3 * q3;
            float n4q3 = N4 * q3;

            float2 u0 = unpack2(rp.x);   // a1, a2
            float2 u1 = unpack2(rp.y);   // b3x, b3y
            float2 u2 = unpack2(rp.z);   // b3z, b4x
            float2 u3 = unpack2(rp.w);   // b4y, b4z
            float2 u4 = unpack2(rq.x);   // b5x, b5y
            float2 u5 = unpack2(rq.y);   // b5z, -
            float a1 = u0.x, a2 = u0.y;
            float b3x = u1.x, b3y = u1.y, b3z = u2.x;
            float b4x = u2.y, b4y = u3.x, b4z = u3.y;
            float b5x = u4.x, b5y = u4.y, b5z = u5.x;

            // out0: paths (0,0,0) and (1,1,0)
            float m0 = s0 * a1;
            m0 = fmaf(s1x, b4x, m0);
            m0 = fmaf(s1y, b4y, m0);
            m0 = fmaf(s1z, b4z, m0);

            // out1: paths (0,1,1), (1,0,1), (1,2,1)
            float m1x = fmaf(D0 * s1x, a2,
                        fmaf(s0, b3x,
                        fmaf(-(n2q2 + n1q4), b5x,
                        fmaf(n3q1, b5y, n1q0 * b5z))));
            float m1y = fmaf(D1 * s1y, a2,
                        fmaf(s0, b3y,
                        fmaf(n4q1, b5x,
                        fmaf(n2q2, b5y, n4q3 * b5z))));
            float m1z = fmaf(D0 * s1z, a2,
                        fmaf(s0, b3z,
                        fmaf(n1q0, b5x,
                        fmaf(n3q3, b5y, (n1q4 - n2q2) * b5z))));

            // SMEM-staged transpose (conflict-free: stride 3 coprime with 32 banks)
            b[lane]              = m0;
            b[32 + 3 * lane + 0] = m1x;
            b[32 + 3 * lane + 1] = m1y;
            b[32 + 3 * lane + 2] = m1z;
            __syncwarp();
            float4 v4 = *reinterpret_cast<float4*>(b + 4 * lane);
            float* dptr = out + (size_t)dst * 128 + 4 * lane;
            asm volatile("red.global.add.v4.f32 [%0], {%1,%2,%3,%4};"
                         :: "l"(dptr), "f"(v4.x), "f"(v4.y), "f"(v4.z), "f"(v4.w) : "memory");
            __syncwarp();

            sv = nsv;
        }
    }
}

// ---------------- launch ----------------
extern "C" void kernel_launch(void* const* d_in, const int* in_sizes, int n_in,
                              void* d_out, int out_size) {
    const float* feat = (const float*)d_in[0];
    const float* sh   = (const float*)d_in[1];
    const int*   eidx = (const int*)d_in[2];
    const float* W    = (const float*)d_in[3];
    int n_nodes = in_sizes[0] / 128;
    int n_edges = in_sizes[2] / 2;

    void* cnt_ptr = nullptr;
    cudaGetSymbolAddress(&cnt_ptr, g_cnt);

    cudaMemsetAsync(d_out, 0, (size_t)out_size * sizeof(float));
    cudaMemsetAsync(cnt_ptr, 0, (size_t)n_nodes * sizeof(int));

    int eb = (n_edges + 255) / 256;
    hist_kernel<<<eb, 256>>>(eidx, n_edges);
    scan_kernel<<<1, 1024>>>(n_nodes);
    scatter_kernel<<<eb, 256>>>(eidx, n_edges);

    int warps_needed = (n_nodes + NPW - 1) / NPW;
    int pre_blocks = (warps_needed + 7) / 8;
    precompute_kernel<<<pre_blocks, 256>>>(feat, W, n_nodes);

    edge_kernel<<<2048, 256>>>(sh, (float*)d_out, n_edges);
}

// round 15
// speedup vs baseline: 1.0324x; 1.0324x over previous
#include <cuda_runtime.h>
#include <cuda_fp16.h>
#include <math.h>

// ---------------- problem constants ----------------
#define MAX_NODES 50000
#define MAX_EDGES 800000

// fp16-compressed per-node records (channel order): per lane 12 halves = uint4 + uint2 (24B)
__device__ uint4 g_node4[MAX_NODES * 32];
__device__ uint2 g_node2[MAX_NODES * 32];

// src-sorted edge metadata: (src, dst, e, pad)
__device__ int4 g_meta[MAX_EDGES];
__device__ int g_cnt[MAX_NODES];
__device__ int g_pos[MAX_NODES];

// ---- constants derived from the reference's (non-standard) CG formula ----
#define ALPHA0 0.125f
#define ALPHA1 0.10206207261596575f
#define D0 0.6666666666666666f
#define D1 0.3333333333333333f
#define E0 0.6963106238227914f
#define E1 0.17407765595569785f
#define N1 0.48888007f
#define N2 0.04704256f
#define N3 0.06111001f
#define N4 0.12222002f

#define NPW 4   // nodes per warp in precompute

static __device__ __forceinline__ unsigned pack2(float a, float b) {
    half2 h = __floats2half2_rn(a, b);
    return *reinterpret_cast<unsigned*>(&h);
}
static __device__ __forceinline__ float2 unpack2(unsigned u) {
    half2 h = *reinterpret_cast<half2*>(&u);
    return __half22float2(h);
}

// ---------------- counting sort of edges by src ----------------
__global__ void hist_kernel(const int* __restrict__ eidx, int n_edges) {
    int e = blockIdx.x * blockDim.x + threadIdx.x;
    if (e < n_edges) atomicAdd(&g_cnt[eidx[e]], 1);
}

__global__ void scan_kernel(int n_nodes) {   // single block, 1024 threads
    __shared__ int ssum[1024];
    int t = threadIdx.x;
    const int SEG = (MAX_NODES + 1023) / 1024;
    int base = t * SEG;
    int s = 0;
    for (int i = 0; i < SEG; i++) {
        int idx = base + i;
        if (idx < n_nodes) s += g_cnt[idx];
    }
    ssum[t] = s;
    __syncthreads();
    for (int d = 1; d < 1024; d <<= 1) {
        int v = (t >= d) ? ssum[t - d] : 0;
        __syncthreads();
        ssum[t] += v;
        __syncthreads();
    }
    int run = (t == 0) ? 0 : ssum[t - 1];
    for (int i = 0; i < SEG; i++) {
        int idx = base + i;
        if (idx < n_nodes) {
            g_pos[idx] = run;
            run += g_cnt[idx];
        }
    }
}

__global__ void scatter_kernel(const int* __restrict__ eidx, int n_edges) {
    int e = blockIdx.x * blockDim.x + threadIdx.x;
    if (e < n_edges) {
        int s = eidx[e];
        int d = eidx[n_edges + e];
        int p = atomicAdd(&g_pos[s], 1);
        g_meta[p] = make_int4(s, d, e, 0);
    }
}

// ---------------- per-node precompute: 4 nodes/warp, lane = channel ----------------
__global__ void __launch_bounds__(256) precompute_kernel(const float* __restrict__ feat,
                                                         const float* __restrict__ W,
                                                         int n_nodes) {
    __shared__ float Ws[5 * 1024];
    __shared__ float4 xs[8][NPW * 32];

    for (int i = threadIdx.x; i < 5 * 1024; i += blockDim.x) {
        int p = i >> 10;
        float s = (p == 0 || p == 3) ? ALPHA0 : ALPHA1;
        Ws[i] = s * W[i];
    }
    __syncthreads();

    int lane = threadIdx.x & 31;
    int wl   = threadIdx.x >> 5;
    int warp = (blockIdx.x * blockDim.x + threadIdx.x) >> 5;
    int nwarp = (gridDim.x * blockDim.x) >> 5;

    for (int nb = warp * NPW; nb < n_nodes; nb += nwarp * NPW) {
        #pragma unroll
        for (int nn = 0; nn < NPW; nn++) {
            int n = nb + nn;
            float4 v = make_float4(0.f, 0.f, 0.f, 0.f);
            if (n < n_nodes) {
                const float* x = feat + (size_t)n * 128;
                v.x = x[lane];
                v.y = x[32 + 3 * lane];
                v.z = x[33 + 3 * lane];
                v.w = x[34 + 3 * lane];
            }
            xs[wl][nn * 32 + lane] = v;
        }
        __syncwarp();

        float a1[NPW], a2[NPW], b3[NPW][3], b4[NPW][3], b5[NPW][3];
        #pragma unroll
        for (int nn = 0; nn < NPW; nn++) {
            a1[nn] = 0.f; a2[nn] = 0.f;
            #pragma unroll
            for (int k = 0; k < 3; k++) { b3[nn][k] = 0.f; b4[nn][k] = 0.f; b5[nn][k] = 0.f; }
        }

        #pragma unroll 4
        for (int u = 0; u < 32; u++) {
            float w0 = Ws[          u * 32 + lane];
            float w1 = Ws[1024 +    u * 32 + lane];
            float w2 = Ws[2048 +    u * 32 + lane];
            float w3 = Ws[3072 +    u * 32 + lane];
            float w4 = Ws[4096 +    u * 32 + lane];
            #pragma unroll
            for (int nn = 0; nn < NPW; nn++) {
                float4 v = xs[wl][nn * 32 + u];   // broadcast
                a1[nn] = fmaf(v.x, w0, a1[nn]);
                a2[nn] = fmaf(v.x, w1, a2[nn]);
                b3[nn][0] = fmaf(v.y, w2, b3[nn][0]);
                b3[nn][1] = fmaf(v.z, w2, b3[nn][1]);
                b3[nn][2] = fmaf(v.w, w2, b3[nn][2]);
                b4[nn][0] = fmaf(v.y, w3, b4[nn][0]);
                b4[nn][1] = fmaf(v.z, w3, b4[nn][1]);
                b4[nn][2] = fmaf(v.w, w3, b4[nn][2]);
                b5[nn][0] = fmaf(v.y, w4, b5[nn][0]);
                b5[nn][1] = fmaf(v.z, w4, b5[nn][1]);
                b5[nn][2] = fmaf(v.w, w4, b5[nn][2]);
            }
        }

        #pragma unroll
        for (int nn = 0; nn < NPW; nn++) {
            int n = nb + nn;
            if (n >= n_nodes) break;
            float c30 = b3[nn][0] * D0, c31 = b3[nn][1] * D1, c32 = b3[nn][2] * D0;
            float c40 = b4[nn][0] * E0, c41 = b4[nn][1] * E1, c42 = b4[nn][2] * E0;
            uint4 p;
            p.x = pack2(a1[nn], a2[nn]);
            p.y = pack2(c30, c31);
            p.z = pack2(c32, c40);
            p.w = pack2(c41, c42);
            uint2 q;
            q.x = pack2(b5[nn][0], b5[nn][1]);
            q.y = pack2(b5[nn][2], 0.f);
            g_node4[n * 32 + lane] = p;
            g_node2[n * 32 + lane] = q;
        }
        __syncwarp();
    }
}

// ---------------- edge kernel: R10 pipelined push body over block-contiguous SORTED ranges ----------------
// Block b owns sorted-edge range [b*per_block, (b+1)*per_block). Its 8 warps stride the range
// (1 edge/warp/iteration, independent, prefetched) so same-src records L1-hit within the SM.
__global__ void __launch_bounds__(256) edge_kernel(const float* __restrict__ sh,
                                                   float* __restrict__ out,
                                                   int n_edges) {
    __shared__ __align__(16) float buf[8][128];
    const unsigned FULL = 0xFFFFFFFFu;
    int lane = threadIdx.x & 31;
    int wl   = threadIdx.x >> 5;
    float* b = buf[wl];

    int per_block = (n_edges + gridDim.x - 1) / gridDim.x;
    int beg = blockIdx.x * per_block;
    int end = min(beg + per_block, n_edges);

    int e = beg + wl;   // 8 warps stride the block's contiguous range
    int4 meta;
    float sv = 0.f;
    if (e < end) {
        meta = g_meta[e];                                   // 16B broadcast load
        sv = (lane < 9) ? sh[(size_t)meta.z * 9 + lane] : 0.f;
    }

    while (e < end) {
        int src = meta.x;
        int dst = meta.y;

        // record gather (sorted ranges -> mostly L1 hits after first touch in this SM)
        uint4 rp = g_node4[src * 32 + lane];
        uint2 rq = g_node2[src * 32 + lane];

        // prefetch next edge's meta + sh while the gather is in flight
        int en = e + 8;
        int4 nmeta;
        float nsv = 0.f;
        if (en < end) {
            nmeta = g_meta[en];
            nsv = (lane < 9) ? sh[(size_t)nmeta.z * 9 + lane] : 0.f;
        }

        // broadcast sh components
        float s0  = __shfl_sync(FULL, sv, 0);
        float s1x = __shfl_sync(FULL, sv, 1);
        float s1y = __shfl_sync(FULL, sv, 2);
        float s1z = __shfl_sync(FULL, sv, 3);
        float q0  = __shfl_sync(FULL, sv, 4);
        float q1v = __shfl_sync(FULL, sv, 5);
        float q2  = __shfl_sync(FULL, sv, 6);
        float q3  = __shfl_sync(FULL, sv, 7);
        float q4  = __shfl_sync(FULL, sv, 8);

        // path (1,2,1) sh-contraction terms
        float n2q2 = N2 * q2;
        float n1q4 = N1 * q4;
        float n1q0 = N1 * q0;
        float n3q1 = N3 * q1v;
        float n4q1 = N4 * q1v;
        float n3q3 = N3 * q3;
        float n4q3 = N4 * q3;

        float2 u0 = unpack2(rp.x);   // a1, a2
        float2 u1 = unpack2(rp.y);   // b3x, b3y
        float2 u2 = unpack2(rp.z);   // b3z, b4x
        float2 u3 = unpack2(rp.w);   // b4y, b4z
        float2 u4 = unpack2(rq.x);   // b5x, b5y
        float2 u5 = unpack2(rq.y);   // b5z, -
        float a1 = u0.x, a2 = u0.y;
        float b3x = u1.x, b3y = u1.y, b3z = u2.x;
        float b4x = u2.y, b4y = u3.x, b4z = u3.y;
        float b5x = u4.x, b5y = u4.y, b5z = u5.x;

        // out0: paths (0,0,0) and (1,1,0)
        float m0 = s0 * a1;
        m0 = fmaf(s1x, b4x, m0);
        m0 = fmaf(s1y, b4y, m0);
        m0 = fmaf(s1z, b4z, m0);

        // out1: paths (0,1,1), (1,0,1), (1,2,1)
        float m1x = fmaf(D0 * s1x, a2,
                    fmaf(s0, b3x,
                    fmaf(-(n2q2 + n1q4), b5x,
                    fmaf(n3q1, b5y, n1q0 * b5z))));
        float m1y = fmaf(D1 * s1y, a2,
                    fmaf(s0, b3y,
                    fmaf(n4q1, b5x,
                    fmaf(n2q2, b5y, n4q3 * b5z))));
        float m1z = fmaf(D0 * s1z, a2,
                    fmaf(s0, b3z,
                    fmaf(n1q0, b5x,
                    fmaf(n3q3, b5y, (n1q4 - n2q2) * b5z))));

        // SMEM-staged transpose (conflict-free: stride 3 coprime with 32 banks)
        b[lane]              = m0;
        b[32 + 3 * lane + 0] = m1x;
        b[32 + 3 * lane + 1] = m1y;
        b[32 + 3 * lane + 2] = m1z;
        __syncwarp();
        float4 v4 = *reinterpret_cast<float4*>(b + 4 * lane);
        float* dptr = out + (size_t)dst * 128 + 4 * lane;
        asm volatile("red.global.add.v4.f32 [%0], {%1,%2,%3,%4};"
                     :: "l"(dptr), "f"(v4.x), "f"(v4.y), "f"(v4.z), "f"(v4.w) : "memory");
        __syncwarp();

        e = en; meta = nmeta; sv = nsv;
    }
}

// ---------------- launch ----------------
extern "C" void kernel_launch(void* const* d_in, const int* in_sizes, int n_in,
                              void* d_out, int out_size) {
    const float* feat = (const float*)d_in[0];
    const float* sh   = (const float*)d_in[1];
    const int*   eidx = (const int*)d_in[2];
    const float* W    = (const float*)d_in[3];
    int n_nodes = in_sizes[0] / 128;
    int n_edges = in_sizes[2] / 2;

    void* cnt_ptr = nullptr;
    cudaGetSymbolAddress(&cnt_ptr, g_cnt);

    cudaMemsetAsync(d_out, 0, (size_t)out_size * sizeof(float));
    cudaMemsetAsync(cnt_ptr, 0, (size_t)n_nodes * sizeof(int));

    int eb = (n_edges + 255) / 256;
    hist_kernel<<<eb, 256>>>(eidx, n_edges);
    scan_kernel<<<1, 1024>>>(n_nodes);
    scatter_kernel<<<eb, 256>>>(eidx, n_edges);

    int warps_needed = (n_nodes + NPW - 1) / NPW;
    int pre_blocks = (warps_needed + 7) / 8;
    precompute_kernel<<<pre_blocks, 256>>>(feat, W, n_nodes);

    edge_kernel<<<2048, 256>>>(sh, (float*)d_out, n_edges);
}

// round 16
// speedup vs baseline: 1.4360x; 1.3910x over previous
#include <cuda_runtime.h>
#include <cuda_fp16.h>
#include <math.h>

// ---------------- problem constants ----------------
#define MAX_NODES 50000

// fp16-compressed per-node records (channel order): per lane 12 halves = uint4 + uint2 (24B)
__device__ uint4 g_node4[MAX_NODES * 32];
__device__ uint2 g_node2[MAX_NODES * 32];

// ---- constants derived from the reference's (non-standard) CG formula ----
#define ALPHA0 0.125f
#define ALPHA1 0.10206207261596575f
#define D0 0.6666666666666666f
#define D1 0.3333333333333333f
#define E0 0.6963106238227914f
#define E1 0.17407765595569785f
#define N1 0.48888007f
#define N2 0.04704256f
#define N3 0.06111001f
#define N4 0.12222002f

#define NPW 4   // nodes per warp in precompute (2 f32x2-packed pairs)

static __device__ __forceinline__ unsigned pack2(float a, float b) {
    half2 h = __floats2half2_rn(a, b);
    return *reinterpret_cast<unsigned*>(&h);
}
static __device__ __forceinline__ float2 unpack2(unsigned u) {
    half2 h = *reinterpret_cast<half2*>(&u);
    return __half22float2(h);
}

// packed f32x2 helpers
static __device__ __forceinline__ unsigned long long packf2(float a, float b) {
    unsigned long long r;
    asm("mov.b64 %0, {%1, %2};" : "=l"(r) : "f"(a), "f"(b));
    return r;
}
static __device__ __forceinline__ void unpackf2(unsigned long long v, float& lo, float& hi) {
    asm("mov.b64 {%0, %1}, %2;" : "=f"(lo), "=f"(hi) : "l"(v));
}
static __device__ __forceinline__ unsigned long long fma2(unsigned long long a,
                                                          unsigned long long b,
                                                          unsigned long long c) {
    unsigned long long d;
    asm("fma.rn.f32x2 %0, %1, %2, %3;" : "=l"(d) : "l"(a), "l"(b), "l"(c));
    return d;
}

// ---------------- per-node precompute: 2 node-pairs/warp via packed f32x2 FMA ----------------
__global__ void __launch_bounds__(256) precompute_kernel(const float* __restrict__ feat,
                                                         const float* __restrict__ W,
                                                         int n_nodes) {
    __shared__ float Ws[5 * 1024];
    __shared__ __align__(16) float4 xsp[8][2][32][2];   // [warp][pair][u][half]: packed node-pair inputs

    for (int i = threadIdx.x; i < 5 * 1024; i += blockDim.x) {
        int p = i >> 10;
        float s = (p == 0 || p == 3) ? ALPHA0 : ALPHA1;
        Ws[i] = s * W[i];
    }
    __syncthreads();

    int lane = threadIdx.x & 31;
    int wl   = threadIdx.x >> 5;
    int warp = (blockIdx.x * blockDim.x + threadIdx.x) >> 5;
    int nwarp = (gridDim.x * blockDim.x) >> 5;

    for (int nb = warp * NPW; nb < n_nodes; nb += nwarp * NPW) {
        // stage packed pairs: xsp[..][0] = (x0@n0,x0@n1,y0@n0,y0@n1), xsp[..][1] = (y1.., y2..)
        #pragma unroll
        for (int p = 0; p < 2; p++) {
            int n0 = nb + 2 * p, n1 = n0 + 1;
            float4 A = make_float4(0.f, 0.f, 0.f, 0.f);
            float4 B = make_float4(0.f, 0.f, 0.f, 0.f);
            if (n0 < n_nodes) {
                const float* x = feat + (size_t)n0 * 128;
                A = make_float4(x[lane], x[32 + 3 * lane], x[33 + 3 * lane], x[34 + 3 * lane]);
            }
            if (n1 < n_nodes) {
                const float* x = feat + (size_t)n1 * 128;
                B = make_float4(x[lane], x[32 + 3 * lane], x[33 + 3 * lane], x[34 + 3 * lane]);
            }
            xsp[wl][p][lane][0] = make_float4(A.x, B.x, A.y, B.y);
            xsp[wl][p][lane][1] = make_float4(A.z, B.z, A.w, B.w);
        }
        __syncwarp();

        // acc[pair][11]: a1,a2,b3x,b3y,b3z,b4x,b4y,b4z,b5x,b5y,b5z (each holds node-pair)
        unsigned long long acc[2][11];
        #pragma unroll
        for (int p = 0; p < 2; p++)
            #pragma unroll
            for (int k = 0; k < 11; k++) acc[p][k] = 0ull;

        #pragma unroll 2
        for (int u = 0; u < 32; u++) {
            float w0 = Ws[          u * 32 + lane];
            float w1 = Ws[1024 +    u * 32 + lane];
            float w2 = Ws[2048 +    u * 32 + lane];
            float w3 = Ws[3072 +    u * 32 + lane];
            float w4 = Ws[4096 +    u * 32 + lane];
            unsigned long long W0 = packf2(w0, w0);
            unsigned long long W1 = packf2(w1, w1);
            unsigned long long W2 = packf2(w2, w2);
            unsigned long long W3 = packf2(w3, w3);
            unsigned long long W4 = packf2(w4, w4);
            #pragma unroll
            for (int p = 0; p < 2; p++) {
                ulonglong2 q0 = *reinterpret_cast<const ulonglong2*>(&xsp[wl][p][u][0]);
                ulonglong2 q1 = *reinterpret_cast<const ulonglong2*>(&xsp[wl][p][u][1]);
                unsigned long long x0 = q0.x, y0 = q0.y, y1 = q1.x, y2 = q1.y;
                acc[p][0]  = fma2(x0, W0, acc[p][0]);
                acc[p][1]  = fma2(x0, W1, acc[p][1]);
                acc[p][2]  = fma2(y0, W2, acc[p][2]);
                acc[p][3]  = fma2(y1, W2, acc[p][3]);
                acc[p][4]  = fma2(y2, W2, acc[p][4]);
                acc[p][5]  = fma2(y0, W3, acc[p][5]);
                acc[p][6]  = fma2(y1, W3, acc[p][6]);
                acc[p][7]  = fma2(y2, W3, acc[p][7]);
                acc[p][8]  = fma2(y0, W4, acc[p][8]);
                acc[p][9]  = fma2(y1, W4, acc[p][9]);
                acc[p][10] = fma2(y2, W4, acc[p][10]);
            }
        }

        // epilogue: unpack each half, fold diagonal CG factors, store fp16 record
        #pragma unroll
        for (int p = 0; p < 2; p++) {
            float v[11][2];
            #pragma unroll
            for (int k = 0; k < 11; k++) unpackf2(acc[p][k], v[k][0], v[k][1]);
            #pragma unroll
            for (int h = 0; h < 2; h++) {
                int n = nb + 2 * p + h;
                if (n < n_nodes) {
                    float a1 = v[0][h], a2 = v[1][h];
                    float c30 = v[2][h] * D0, c31 = v[3][h] * D1, c32 = v[4][h] * D0;
                    float c40 = v[5][h] * E0, c41 = v[6][h] * E1, c42 = v[7][h] * E0;
                    uint4 pk;
                    pk.x = pack2(a1, a2);
                    pk.y = pack2(c30, c31);
                    pk.z = pack2(c32, c40);
                    pk.w = pack2(c41, c42);
                    uint2 qk;
                    qk.x = pack2(v[8][h], v[9][h]);
                    qk.y = pack2(v[10][h], 0.f);
                    g_node4[n * 32 + lane] = pk;
                    g_node2[n * 32 + lane] = qk;
                }
            }
        }
        __syncwarp();
    }
}

// ---------------- dual-edge kernel (R13 structure): half-warp per edge, SMEM transpose, red.v4 ----------------
__global__ void __launch_bounds__(256, 6) edge_kernel(const float* __restrict__ sh,
                                                      const int* __restrict__ eidx,
                                                      float* __restrict__ out,
                                                      int n_edges) {
    // per-warp staging: 2 edges x 144 floats (pad 144 makes all STS conflict-free across halves)
    __shared__ __align__(16) float buf[8][2 * 144];
    const unsigned FULL = 0xFFFFFFFFu;
    int lane   = threadIdx.x & 31;
    int lane16 = lane & 15;
    int half   = lane >> 4;
    int wl     = threadIdx.x >> 5;
    int warp   = (blockIdx.x * blockDim.x + threadIdx.x) >> 5;
    int nwarp  = (gridDim.x * blockDim.x) >> 5;
    float* b = buf[wl] + half * 144;

    int e = warp * 2;            // n_edges is even; pairs stay complete
    int stride = nwarp * 2;

    int src_h = 0, dst_h = 0;
    float sv = 0.f;
    if (e < n_edges) {
        int tmp = 0;
        if (lane < 4) tmp = eidx[(lane >> 1) * n_edges + e + (lane & 1)];
        src_h = __shfl_sync(FULL, tmp, half);
        dst_h = __shfl_sync(FULL, tmp, 2 + half);
        sv = (lane16 < 9) ? sh[(size_t)(e + half) * 9 + lane16] : 0.f;
    }

    while (e < n_edges) {
        // record gather for both channels of this half's edge (issued first)
        uint4 rp0 = g_node4[src_h * 32 + lane16];
        uint4 rp1 = g_node4[src_h * 32 + 16 + lane16];
        uint2 rq0 = g_node2[src_h * 32 + lane16];
        uint2 rq1 = g_node2[src_h * 32 + 16 + lane16];

        // prefetch next pair's idx + sh while gather is in flight
        int en = e + stride;
        int nsrc = 0, ndst = 0;
        float nsv = 0.f;
        if (en < n_edges) {
            int tmp = 0;
            if (lane < 4) tmp = eidx[(lane >> 1) * n_edges + en + (lane & 1)];
            nsrc = __shfl_sync(FULL, tmp, half);
            ndst = __shfl_sync(FULL, tmp, 2 + half);
            nsv = (lane16 < 9) ? sh[(size_t)(en + half) * 9 + lane16] : 0.f;
        }

        // width-16 broadcasts: each half gets its own edge's sh
        float s0  = __shfl_sync(FULL, sv, 0, 16);
        float s1x = __shfl_sync(FULL, sv, 1, 16);
        float s1y = __shfl_sync(FULL, sv, 2, 16);
        float s1z = __shfl_sync(FULL, sv, 3, 16);
        float q0  = __shfl_sync(FULL, sv, 4, 16);
        float q1v = __shfl_sync(FULL, sv, 5, 16);
        float q2  = __shfl_sync(FULL, sv, 6, 16);
        float q3  = __shfl_sync(FULL, sv, 7, 16);
        float q4  = __shfl_sync(FULL, sv, 8, 16);

        float n2q2 = N2 * q2;
        float n1q4 = N1 * q4;
        float n1q0 = N1 * q0;
        float S00 = -(n2q2 + n1q4), S01 = N3 * q1v, S02 = n1q0;
        float S10 = N4 * q1v,       S11 = n2q2,     S12 = N4 * q3;
        float S20 = n1q0,           S21 = N3 * q3,  S22 = n1q4 - n2q2;
        float ds1x = D0 * s1x, ds1y = D1 * s1y, ds1z = D0 * s1z;

        #pragma unroll
        for (int c = 0; c < 2; c++) {
            uint4 rp = c ? rp1 : rp0;
            uint2 rq = c ? rq1 : rq0;
            int ch = lane16 + 16 * c;

            float2 u0 = unpack2(rp.x);   // a1, a2
            float2 u1 = unpack2(rp.y);   // b3x, b3y
            float2 u2 = unpack2(rp.z);   // b3z, b4x
            float2 u3 = unpack2(rp.w);   // b4y, b4z
            float2 u4 = unpack2(rq.x);   // b5x, b5y
            float2 u5 = unpack2(rq.y);   // b5z, -
            float a1 = u0.x, a2 = u0.y;
            float b3x = u1.x, b3y = u1.y, b3z = u2.x;
            float b4x = u2.y, b4y = u3.x, b4z = u3.y;
            float b5x = u4.x, b5y = u4.y, b5z = u5.x;

            float m0 = s0 * a1;
            m0 = fmaf(s1x, b4x, m0);
            m0 = fmaf(s1y, b4y, m0);
            m0 = fmaf(s1z, b4z, m0);

            float m1x = fmaf(ds1x, a2,
                        fmaf(s0, b3x,
                        fmaf(S00, b5x,
                        fmaf(S01, b5y, S02 * b5z))));
            float m1y = fmaf(ds1y, a2,
                        fmaf(s0, b3y,
                        fmaf(S10, b5x,
                        fmaf(S11, b5y, S12 * b5z))));
            float m1z = fmaf(ds1z, a2,
                        fmaf(s0, b3z,
                        fmaf(S20, b5x,
                        fmaf(S21, b5y, S22 * b5z))));

            b[ch]              = m0;
            b[32 + 3 * ch + 0] = m1x;
            b[32 + 3 * ch + 1] = m1y;
            b[32 + 3 * ch + 2] = m1z;
        }
        __syncwarp();

        // two vector-red rounds per half (64 floats each)
        float4 v0 = *reinterpret_cast<float4*>(b + 4 * lane16);
        float4 v1 = *reinterpret_cast<float4*>(b + 64 + 4 * lane16);
        float* dbase = out + (size_t)dst_h * 128 + 4 * lane16;
        asm volatile("red.global.add.v4.f32 [%0], {%1,%2,%3,%4};"
                     :: "l"(dbase), "f"(v0.x), "f"(v0.y), "f"(v0.z), "f"(v0.w) : "memory");
        asm volatile("red.global.add.v4.f32 [%0], {%1,%2,%3,%4};"
                     :: "l"(dbase + 64), "f"(v1.x), "f"(v1.y), "f"(v1.z), "f"(v1.w) : "memory");
        __syncwarp();

        e = en; src_h = nsrc; dst_h = ndst; sv = nsv;
    }
}

// ---------------- launch ----------------
extern "C" void kernel_launch(void* const* d_in, const int* in_sizes, int n_in,
                              void* d_out, int out_size) {
    const float* feat = (const float*)d_in[0];
    const float* sh   = (const float*)d_in[1];
    const int*   eidx = (const int*)d_in[2];
    const float* W    = (const float*)d_in[3];
    int n_nodes = in_sizes[0] / 128;
    int n_edges = in_sizes[2] / 2;

    cudaMemsetAsync(d_out, 0, (size_t)out_size * sizeof(float));

    int warps_needed = (n_nodes + NPW - 1) / NPW;
    int pre_blocks = (warps_needed + 7) / 8;
    precompute_kernel<<<pre_blocks, 256>>>(feat, W, n_nodes);

    edge_kernel<<<2048, 256>>>(sh, eidx, (float*)d_out, n_edges);
}